// round 2
// baseline (speedup 1.0000x reference)
#include <cuda_runtime.h>
#include <math.h>

// Problem dims
#define BB 8
#define LL 4096
#define DD 1024
#define MTOT (BB * LL)            // 32768
#define NCHUNK 16
#define TCHUNK (LL / NCHUNK)      // 256
#define NCHAN (BB * DD)           // 8192

// Scratch (device globals — allocation-free per harness rules)
__device__ float g_G[MTOT * DD];     // sigmoid gate g  (134 MB)
__device__ float g_C[MTOT * DD];     // tanh candidate c (134 MB)
__device__ float g_AggA[NCHUNK * NCHAN];
__device__ float g_AggB[NCHUNK * NCHAN];
__device__ float g_Carry[NCHUNK * NCHAN];

// ---------------------------------------------------------------------------
// Fused dual-GEMM + bias + activation.
// Computes Y = x @ W^T + bias for W in {Wg, Wh}; applies sigmoid -> g_G or
// tanh -> g_C. Virtual N = 2048 (first 1024 cols: Wg, last 1024: Wh).
// Tile: BM=128, BN=64, BK=16; 256 threads; 8x4 per-thread microtile.
// ---------------------------------------------------------------------------
__global__ __launch_bounds__(256, 2)
void gemm_act_kernel(const float* __restrict__ x,
                     const float* __restrict__ Wg, const float* __restrict__ bg,
                     const float* __restrict__ Wh, const float* __restrict__ bh)
{
    __shared__ float As[16][132];   // [k][m], padded (132*4B stride, 16B-aligned rows)
    __shared__ float Bs[16][68];    // [k][n], padded

    const int tid = threadIdx.x;
    const int tx = tid & 15;        // 0..15 -> 4 cols each
    const int ty = tid >> 4;        // 0..15 -> 8 rows each

    const int ntile = blockIdx.x;   // 0..31 (virtual N=2048)
    const int m0 = blockIdx.y * 128;
    const bool second = (ntile >= 16);
    const int n0 = (ntile & 15) * 64;      // column within its 1024-wide output
    const float* __restrict__ W = second ? Wh : Wg;
    const float* __restrict__ bias = second ? bh : bg;
    float* __restrict__ out = second ? g_C : g_G;

    // x-tile load mapping: 2 float4 per thread
    const int xrow0 = tid >> 2;           // 0..63
    const int xkv = tid & 3;              // which float4 along K
    // W-tile load mapping: 1 float4 per thread
    const int wrow = tid >> 2;            // 0..63
    const int wkv = tid & 3;

    float acc[8][4];
#pragma unroll
    for (int i = 0; i < 8; i++)
#pragma unroll
        for (int j = 0; j < 4; j++) acc[i][j] = 0.f;

    for (int kt = 0; kt < DD; kt += 16) {
        // load x tile [128][16] -> As[k][m]
#pragma unroll
        for (int h = 0; h < 2; h++) {
            const int row = xrow0 + h * 64;
            float4 v = *(const float4*)&x[(m0 + row) * DD + kt + xkv * 4];
            As[xkv * 4 + 0][row] = v.x;
            As[xkv * 4 + 1][row] = v.y;
            As[xkv * 4 + 2][row] = v.z;
            As[xkv * 4 + 3][row] = v.w;
        }
        // load W tile [64][16] -> Bs[k][n]
        {
            float4 v = *(const float4*)&W[(n0 + wrow) * DD + kt + wkv * 4];
            Bs[wkv * 4 + 0][wrow] = v.x;
            Bs[wkv * 4 + 1][wrow] = v.y;
            Bs[wkv * 4 + 2][wrow] = v.z;
            Bs[wkv * 4 + 3][wrow] = v.w;
        }
        __syncthreads();

#pragma unroll
        for (int kk = 0; kk < 16; kk++) {
            float4 a0 = *(const float4*)&As[kk][ty * 8];
            float4 a1 = *(const float4*)&As[kk][ty * 8 + 4];
            float4 bv = *(const float4*)&Bs[kk][tx * 4];
            float av[8] = {a0.x, a0.y, a0.z, a0.w, a1.x, a1.y, a1.z, a1.w};
            float bw[4] = {bv.x, bv.y, bv.z, bv.w};
#pragma unroll
            for (int i = 0; i < 8; i++)
#pragma unroll
                for (int j = 0; j < 4; j++)
                    acc[i][j] = fmaf(av[i], bw[j], acc[i][j]);
        }
        __syncthreads();
    }

    // epilogue: bias + activation + store
    float4 bvec = *(const float4*)&bias[n0 + tx * 4];
    float bb4[4] = {bvec.x, bvec.y, bvec.z, bvec.w};
#pragma unroll
    for (int i = 0; i < 8; i++) {
        const int m = m0 + ty * 8 + i;
        float4 o;
        float v[4];
#pragma unroll
        for (int j = 0; j < 4; j++) {
            float t = acc[i][j] + bb4[j];
            if (second) v[j] = tanhf(t);
            else        v[j] = 1.0f / (1.0f + __expf(-t));
        }
        o.x = v[0]; o.y = v[1]; o.z = v[2]; o.w = v[3];
        *(float4*)&out[m * DD + n0 + tx * 4] = o;
    }
}

// ---------------------------------------------------------------------------
// Scan phase A: per (channel, chunk) affine aggregate over TCHUNK steps.
// grid = BB * NCHUNK * (DD/256) = 512 blocks of 256 threads.
// ---------------------------------------------------------------------------
__global__ __launch_bounds__(256)
void scan_aggregate_kernel()
{
    const int bx = blockIdx.x;
    const int dgrp = bx & 3;
    const int chunk = (bx >> 2) & (NCHUNK - 1);
    const int b = bx >> 6;
    const int d = dgrp * 256 + threadIdx.x;

    int base = (b * LL + chunk * TCHUNK) * DD + d;
    float A = 1.0f, Bc = 0.0f;
#pragma unroll 8
    for (int t = 0; t < TCHUNK; t++) {
        float g = g_G[base];
        float c = g_C[base];
        float bt = (1.0f - g) * c;
        Bc = fmaf(g, Bc, bt);
        A *= g;
        base += DD;
    }
    const int ch = b * DD + d;
    g_AggA[chunk * NCHAN + ch] = A;
    g_AggB[chunk * NCHAN + ch] = Bc;
}

// ---------------------------------------------------------------------------
// Scan phase B: sequential scan of chunk aggregates per channel (tiny).
// grid = 32 blocks x 256 threads = 8192 threads.
// ---------------------------------------------------------------------------
__global__ __launch_bounds__(256)
void scan_carry_kernel(const float* __restrict__ hidden)
{
    const int ch = blockIdx.x * 256 + threadIdx.x;
    float h = hidden[ch];
#pragma unroll
    for (int k = 0; k < NCHUNK; k++) {
        g_Carry[k * NCHAN + ch] = h;
        h = fmaf(g_AggA[k * NCHAN + ch], h, g_AggB[k * NCHAN + ch]);
    }
}

// ---------------------------------------------------------------------------
// Scan phase C: re-run recurrence within each chunk from its carry, write out.
// ---------------------------------------------------------------------------
__global__ __launch_bounds__(256)
void scan_apply_kernel(float* __restrict__ out)
{
    const int bx = blockIdx.x;
    const int dgrp = bx & 3;
    const int chunk = (bx >> 2) & (NCHUNK - 1);
    const int b = bx >> 6;
    const int d = dgrp * 256 + threadIdx.x;
    const int ch = b * DD + d;

    int base = (b * LL + chunk * TCHUNK) * DD + d;
    float h = g_Carry[chunk * NCHAN + ch];
#pragma unroll 8
    for (int t = 0; t < TCHUNK; t++) {
        float g = g_G[base];
        float c = g_C[base];
        float bt = (1.0f - g) * c;
        h = fmaf(g, h, bt);
        out[base] = h;
        base += DD;
    }
}

// ---------------------------------------------------------------------------
extern "C" void kernel_launch(void* const* d_in, const int* in_sizes, int n_in,
                              void* d_out, int out_size)
{
    const float* x      = (const float*)d_in[0];
    const float* hidden = (const float*)d_in[1];
    const float* Wg     = (const float*)d_in[2];
    const float* bg     = (const float*)d_in[3];
    const float* Wh     = (const float*)d_in[4];
    const float* bh     = (const float*)d_in[5];
    float* out = (float*)d_out;

    dim3 ggrid(32, MTOT / 128);   // 32 n-tiles (virtual N=2048), 256 m-tiles
    gemm_act_kernel<<<ggrid, 256>>>(x, Wg, bg, Wh, bh);

    scan_aggregate_kernel<<<BB * NCHUNK * (DD / 256), 256>>>();
    scan_carry_kernel<<<NCHAN / 256, 256>>>(hidden);
    scan_apply_kernel<<<BB * NCHUNK * (DD / 256), 256>>>(out);
}

// round 4
// speedup vs baseline: 3.5817x; 3.5817x over previous
#include <cuda_runtime.h>
#include <cstdint>
#include <math.h>

// ---------------- problem dims ----------------
#define BB 8
#define LL 4096
#define DD 1024
#define MTOT (BB * LL)            // 32768
#define NVIRT (2 * DD)            // 2048 virtual N (Wg | Wh)

// GEMM tiling
#define BM 128
#define BN 128
#define BK 32
#define NCH (DD / BK)             // 32 k-chunks
#define NS 3                      // pipeline stages

#define STAGE_A_BYTES (BM * BK * 4)   // 16 KB
#define STAGE_B_BYTES (BN * BK * 4)   // 16 KB
#define STAGE_BYTES (STAGE_A_BYTES + STAGE_B_BYTES)
#define SMEM_NEEDED (NS * STAGE_BYTES)   // 96 KB

// scan chunking
#define NCHUNK 16
#define TCHUNK (LL / NCHUNK)      // 256
#define NCHAN (BB * DD)           // 8192

// ---------------- device scratch ----------------
__device__ float g_G[(size_t)MTOT * DD];     // sigmoid gate
__device__ float g_C[(size_t)MTOT * DD];     // tanh candidate
__device__ float g_AggA[NCHUNK * NCHAN];
__device__ float g_AggB[NCHUNK * NCHAN];
__device__ float g_Carry[NCHUNK * NCHAN];

// ---------------- helpers ----------------
__device__ __forceinline__ uint32_t smem_to_u32(const void* p) {
    uint32_t a;
    asm("{ .reg .u64 t; cvta.to.shared.u64 t, %1; cvt.u32.u64 %0, t; }" : "=r"(a) : "l"(p));
    return a;
}
__device__ __forceinline__ void cp_async16(uint32_t saddr, const void* gaddr) {
    asm volatile("cp.async.cg.shared.global [%0], [%1], 16;" :: "r"(saddr), "l"(gaddr));
}
__device__ __forceinline__ void cp_commit() { asm volatile("cp.async.commit_group;" ::: "memory"); }
__device__ __forceinline__ void cp_wait2() { asm volatile("cp.async.wait_group 2;" ::: "memory"); }

__device__ __forceinline__ void ldsm_x4(uint32_t& r0, uint32_t& r1, uint32_t& r2, uint32_t& r3,
                                        uint32_t addr) {
    asm volatile("ldmatrix.sync.aligned.m8n8.x4.shared.b16 {%0,%1,%2,%3}, [%4];"
                 : "=r"(r0), "=r"(r1), "=r"(r2), "=r"(r3) : "r"(addr));
}
__device__ __forceinline__ uint32_t round_tf32(uint32_t v) {
    uint32_t o;
    asm("cvt.rna.tf32.f32 %0, %1;" : "=r"(o) : "f"(__uint_as_float(v)));
    return o;
}
__device__ __forceinline__ void mma_tf32(float* c, const uint32_t* a, const uint32_t* b) {
    asm volatile(
        "mma.sync.aligned.m16n8k8.row.col.f32.tf32.tf32.f32 "
        "{%0,%1,%2,%3}, {%4,%5,%6,%7}, {%8,%9}, {%0,%1,%2,%3};"
        : "+f"(c[0]), "+f"(c[1]), "+f"(c[2]), "+f"(c[3])
        : "r"(a[0]), "r"(a[1]), "r"(a[2]), "r"(a[3]), "r"(b[0]), "r"(b[1]));
}

// swizzled smem offset for (row, 16B-chunk) with 128B rows
__device__ __forceinline__ uint32_t sw_off(int row, int chunk) {
    return (uint32_t)(row * 128 + ((chunk ^ (row & 7)) << 4));
}

// ---------------------------------------------------------------------------
// tf32 mma.sync GEMM + bias + activation epilogue.
// grid = (NVIRT/BN = 16, MTOT/BM = 256), 256 threads (8 warps, 2x4 m x n).
// Y[m, n] = sum_k X[m,k] * W[n,k]  (+bias, activation)
// ---------------------------------------------------------------------------
__global__ __launch_bounds__(256, 2)
void gemm_mma_kernel(const float* __restrict__ x,
                     const float* __restrict__ Wg, const float* __restrict__ bg,
                     const float* __restrict__ Wh, const float* __restrict__ bh)
{
    extern __shared__ char smem_raw[];
    const uint32_t s0 = smem_to_u32(smem_raw);

    const int tid = threadIdx.x;
    const int wid = tid >> 5;
    const int lane = tid & 31;
    const int wm = wid >> 2;          // 0..1  -> 64-row band
    const int wn = wid & 3;           // 0..3  -> 32-col band

    const int m0 = blockIdx.y * BM;
    const int n0 = blockIdx.x * BN;   // virtual col
    const bool second = (n0 >= DD);
    const int n0r = n0 & (DD - 1);
    const float* __restrict__ W = second ? Wh : Wg;
    const float* __restrict__ bias = second ? bh : bg;
    float* __restrict__ outp = second ? g_C : g_G;

    // ---- load mapping: 4 chunks A + 4 chunks B per thread per stage ----
    // u = i*256 + tid ; row = u>>3 ; chunk = u&7
    const float* xa0 = x + (size_t)m0 * DD;
    const float* wb0 = W + (size_t)n0r * DD;

    auto load_stage = [&](int s, int kc) {
        const uint32_t sa = s0 + (uint32_t)s * STAGE_BYTES;
        const uint32_t sb = sa + STAGE_A_BYTES;
        const int kt = kc * BK;
#pragma unroll
        for (int i = 0; i < 4; i++) {
            int u = i * 256 + tid;
            int r = u >> 3, c = u & 7;
            cp_async16(sa + sw_off(r, c), xa0 + (size_t)r * DD + kt + c * 4);
        }
#pragma unroll
        for (int i = 0; i < 4; i++) {
            int u = i * 256 + tid;
            int r = u >> 3, c = u & 7;
            cp_async16(sb + sw_off(r, c), wb0 + (size_t)r * DD + kt + c * 4);
        }
    };

    float acc[4][4][4];               // [m-tile][n-tile][frag]
#pragma unroll
    for (int i = 0; i < 4; i++)
#pragma unroll
        for (int j = 0; j < 4; j++)
#pragma unroll
            for (int q = 0; q < 4; q++) acc[i][j][q] = 0.f;

    // prologue
    load_stage(0, 0); cp_commit();
    load_stage(1, 1); cp_commit();

    const int q = lane >> 3, rr = lane & 7;

    for (int k = 0; k < NCH; k++) {
        const int kl = k + NS - 1;
        if (kl < NCH) load_stage(kl % NS, kl);
        cp_commit();
        cp_wait2();
        __syncthreads();

        const uint32_t sa = s0 + (uint32_t)(k % NS) * STAGE_BYTES;
        const uint32_t sb = sa + STAGE_A_BYTES;

#pragma unroll
        for (int kk8 = 0; kk8 < 4; kk8++) {      // four k8 steps in BK=32
            const int ch = kk8 * 2;              // 16B-chunk base (k8 = 2 chunks)
            uint32_t afr[4][4];
#pragma unroll
            for (int mt = 0; mt < 4; mt++) {
                // lanes: q=0: rows 0-7 ch, q=1: rows 8-15 ch, q=2: rows 0-7 ch+1, q=3: rows 8-15 ch+1
                int row = wm * 64 + mt * 16 + ((q & 1) << 3) + rr;
                int chunk = ch + (q >> 1);
                ldsm_x4(afr[mt][0], afr[mt][1], afr[mt][2], afr[mt][3],
                        sa + sw_off(row, chunk));
#pragma unroll
                for (int t = 0; t < 4; t++) afr[mt][t] = round_tf32(afr[mt][t]);
            }
            uint32_t bfr[4][2];
#pragma unroll
            for (int p = 0; p < 2; p++) {        // each x4 covers two n8-tiles
                // q=0: ntile p*2 chunk ch (b0); q=1: ntile p*2 chunk ch+1 (b1); q=2,3: ntile p*2+1
                int row = wn * 32 + p * 16 + ((q >> 1) << 3) + rr;
                int chunk = ch + (q & 1);
                uint32_t r0, r1, r2, r3;
                ldsm_x4(r0, r1, r2, r3, sb + sw_off(row, chunk));
                bfr[p * 2 + 0][0] = round_tf32(r0); bfr[p * 2 + 0][1] = round_tf32(r1);
                bfr[p * 2 + 1][0] = round_tf32(r2); bfr[p * 2 + 1][1] = round_tf32(r3);
            }
#pragma unroll
            for (int mt = 0; mt < 4; mt++)
#pragma unroll
                for (int nt = 0; nt < 4; nt++)
                    mma_tf32(acc[mt][nt], afr[mt], bfr[nt]);
        }
        __syncthreads();
    }

    // ---- epilogue: bias + activation, float2 stores ----
    const int crow = lane >> 2;            // 0..7
    const int ccol = (lane & 3) * 2;       // 0,2,4,6
#pragma unroll
    for (int nt = 0; nt < 4; nt++) {
        const int col = wn * 32 + nt * 8 + ccol;
        const float2 bv = *(const float2*)&bias[n0r + col];
#pragma unroll
        for (int mt = 0; mt < 4; mt++) {
#pragma unroll
            for (int h = 0; h < 2; h++) {  // c0/c1 then c2/c3 (row, row+8)
                const int m = m0 + wm * 64 + mt * 16 + crow + h * 8;
                float t0 = acc[mt][nt][h * 2 + 0] + bv.x;
                float t1 = acc[mt][nt][h * 2 + 1] + bv.y;
                float2 o;
                if (second) { o.x = tanhf(t0); o.y = tanhf(t1); }
                else {
                    o.x = 1.0f / (1.0f + __expf(-t0));
                    o.y = 1.0f / (1.0f + __expf(-t1));
                }
                *(float2*)&outp[(size_t)m * DD + n0r + col] = o;
            }
        }
    }
}

// ---------------------------------------------------------------------------
// Scan phase A: per (channel, chunk) affine aggregate over TCHUNK steps.
// ---------------------------------------------------------------------------
__global__ __launch_bounds__(256)
void scan_aggregate_kernel()
{
    const int bx = blockIdx.x;
    const int dgrp = bx & 3;
    const int chunk = (bx >> 2) & (NCHUNK - 1);
    const int b = bx >> 6;
    const int d = dgrp * 256 + threadIdx.x;

    size_t base = ((size_t)(b * LL + chunk * TCHUNK)) * DD + d;
    float A = 1.0f, Bc = 0.0f;
#pragma unroll 8
    for (int t = 0; t < TCHUNK; t++) {
        float g = g_G[base];
        float c = g_C[base];
        float bt = (1.0f - g) * c;
        Bc = fmaf(g, Bc, bt);
        A *= g;
        base += DD;
    }
    const int ch = b * DD + d;
    g_AggA[chunk * NCHAN + ch] = A;
    g_AggB[chunk * NCHAN + ch] = Bc;
}

// ---------------------------------------------------------------------------
// Scan phase B: sequential scan of chunk aggregates per channel.
// ---------------------------------------------------------------------------
__global__ __launch_bounds__(256)
void scan_carry_kernel(const float* __restrict__ hidden)
{
    const int ch = blockIdx.x * 256 + threadIdx.x;
    float h = hidden[ch];
#pragma unroll
    for (int k = 0; k < NCHUNK; k++) {
        g_Carry[k * NCHAN + ch] = h;
        h = fmaf(g_AggA[k * NCHAN + ch], h, g_AggB[k * NCHAN + ch]);
    }
}

// ---------------------------------------------------------------------------
// Scan phase C: apply within-chunk recurrence from carry, write output.
// ---------------------------------------------------------------------------
__global__ __launch_bounds__(256)
void scan_apply_kernel(float* __restrict__ out)
{
    const int bx = blockIdx.x;
    const int dgrp = bx & 3;
    const int chunk = (bx >> 2) & (NCHUNK - 1);
    const int b = bx >> 6;
    const int d = dgrp * 256 + threadIdx.x;
    const int ch = b * DD + d;

    size_t base = ((size_t)(b * LL + chunk * TCHUNK)) * DD + d;
    float h = g_Carry[chunk * NCHAN + ch];
#pragma unroll 8
    for (int t = 0; t < TCHUNK; t++) {
        float g = g_G[base];
        float c = g_C[base];
        float bt = (1.0f - g) * c;
        h = fmaf(g, h, bt);
        out[base] = h;
        base += DD;
    }
}

// ---------------------------------------------------------------------------
extern "C" void kernel_launch(void* const* d_in, const int* in_sizes, int n_in,
                              void* d_out, int out_size)
{
    const float* x      = (const float*)d_in[0];
    const float* hidden = (const float*)d_in[1];
    const float* Wg     = (const float*)d_in[2];
    const float* bg     = (const float*)d_in[3];
    const float* Wh     = (const float*)d_in[4];
    const float* bh     = (const float*)d_in[5];
    float* out = (float*)d_out;

    static bool attr_set = false;
    if (!attr_set) {
        cudaFuncSetAttribute(gemm_mma_kernel,
                             cudaFuncAttributeMaxDynamicSharedMemorySize, SMEM_NEEDED);
        attr_set = true;
    }

    dim3 ggrid(NVIRT / BN, MTOT / BM);   // (16, 256)
    gemm_mma_kernel<<<ggrid, 256, SMEM_NEEDED>>>(x, Wg, bg, Wh, bh);

    scan_aggregate_kernel<<<BB * NCHUNK * (DD / 256), 256>>>();
    scan_carry_kernel<<<NCHAN / 256, 256>>>(hidden);
    scan_apply_kernel<<<BB * NCHUNK * (DD / 256), 256>>>(out);
}